// round 10
// baseline (speedup 1.0000x reference)
#include <cuda_runtime.h>
#include <cstdint>

// FINAL (converged at roofline): Unfold (im2col) — SMEM-staged 8-row tiles
// + TMA bulk stores.
// x: [16, 64, 112, 112] f32 ; out: [16, 576, 112, 112] f32
// out[n, c*9 + kh*3 + kw, h, w] = x[n, c, h+kh-1, w+kw-1] (0 outside)
//
// Block = (n, c, 8-row band). Warp w owns row h0+w: loads 3 aligned float4
// rows (input is L2-resident across the 9x reuse), builds the 9 shifted
// variants via warp shuffle, writes them to SMEM; threads 0..8 then push
// 9 chunks of 3584B (28 full 128B lines, line-aligned) via cp.async.bulk.
//
// Evidence of roofline: DRAM bytes == compulsory 455MB output writes; four
// distinct store mechanisms (STG.128, STG.cs, TMA small/large, persistent
// TMA) all plateau at 5.85-6.0 TB/s = HBM3e pure-write-stream ceiling
// (~3300 B/cyc @NAT, well under the 6300 B/cyc LTS cap). Issue 13%, all
// compute pipes idle.

#define HWDIM 112
#define PLANE (HWDIM * HWDIM)   // 12544
#define ROWS  8
#define BANDS (HWDIM / ROWS)    // 14
#define CHUNK_BYTES (ROWS * HWDIM * 4)   // 3584

__global__ __launch_bounds__(256) void unfold_kernel(
    const float* __restrict__ x, float* __restrict__ out)
{
    __shared__ __align__(16) float sm[9][ROWS][HWDIM];   // 31.5 KB

    const int blk = blockIdx.x;
    const int hb  = blk % BANDS;
    const int nc  = blk / BANDS;            // n*64 + c
    const int h0  = hb * ROWS;

    const int wid  = threadIdx.x >> 5;      // 0..7 -> row h0+wid
    const int lane = threadIdx.x & 31;
    const int h    = h0 + wid;

    const bool wok = lane < 28;
    const int w0 = lane * 4;

    const float* plane = x + (int64_t)nc * PLANE;

    float4 r[3];
#pragma unroll
    for (int i = 0; i < 3; ++i) {
        const int ih = h - 1 + i;
        if (wok && (unsigned)ih < HWDIM)
            r[i] = *reinterpret_cast<const float4*>(plane + ih * HWDIM + w0);
        else
            r[i] = make_float4(0.f, 0.f, 0.f, 0.f);
    }

#pragma unroll
    for (int i = 0; i < 3; ++i) {
        float pw = __shfl_up_sync(0xFFFFFFFFu, r[i].w, 1);
        if (lane == 0) pw = 0.f;                               // left pad
        float nx = __shfl_down_sync(0xFFFFFFFFu, r[i].x, 1);   // lane27 -> 0
        if (wok) {
            *reinterpret_cast<float4*>(&sm[i * 3 + 0][wid][w0]) =
                make_float4(pw, r[i].x, r[i].y, r[i].z);        // kw = -1
            *reinterpret_cast<float4*>(&sm[i * 3 + 1][wid][w0]) = r[i];
            *reinterpret_cast<float4*>(&sm[i * 3 + 2][wid][w0]) =
                make_float4(r[i].y, r[i].z, r[i].w, nx);        // kw = +1
        }
    }

    __syncthreads();
    asm volatile("fence.proxy.async.shared::cta;" ::: "memory");

    // 9 bulk stores, one per kk-plane chunk (3584B contiguous, line-aligned)
    if (threadIdx.x < 9) {
        const int kk = threadIdx.x;
        uint32_t saddr;
        asm("{ .reg .u64 t; cvta.to.shared.u64 t, %1; cvt.u32.u64 %0, t; }"
            : "=r"(saddr) : "l"(&sm[kk][0][0]));
        float* gdst = out + ((int64_t)(nc * 9 + kk) * HWDIM + h0) * HWDIM;
        asm volatile(
            "cp.async.bulk.global.shared::cta.bulk_group [%0], [%1], %2;"
            :: "l"(gdst), "r"(saddr), "n"(CHUNK_BYTES) : "memory");
        asm volatile("cp.async.bulk.commit_group;" ::: "memory");
        asm volatile("cp.async.bulk.wait_group 0;" ::: "memory");
    }
}

extern "C" void kernel_launch(void* const* d_in, const int* in_sizes, int n_in,
                              void* d_out, int out_size)
{
    const float* x = (const float*)d_in[0];
    float* out = (float*)d_out;

    const int blocks = 16 * 64 * BANDS;   // 14336
    unfold_kernel<<<blocks, 256>>>(x, out);
}

// round 11
// speedup vs baseline: 1.0136x; 1.0136x over previous
#include <cuda_runtime.h>
#include <cstdint>

// FINAL: Unfold (im2col) — SMEM-staged 8-row tiles + TMA bulk stores,
// TMA issue spread across all 8 warps (best-occupancy roofline variant).
// x: [16, 64, 112, 112] f32 ; out: [16, 576, 112, 112] f32
// out[n, c*9 + kh*3 + kw, h, w] = x[n, c, h+kh-1, w+kw-1] (0 outside)
//
// Block = (n, c, 8-row band). Warp w owns row h0+w: 3 aligned float4 loads
// (input L2-resident across the 9x reuse), 9 shifted variants via shfl into
// SMEM; lane 0 of warp k issues the bulk store for plane k (warp 0 also
// issues plane 8) — 9 chunks of 3584B, each 28 full 128B lines.
//
// Converged at roofline: DRAM bytes == compulsory 455MB output writes; five
// store configurations (STG.128, STG.cs, TMA 8/16-row, warp-spread TMA,
// persistent TMA) all plateau at 5.85-6.0 TB/s pure-write HBM3e ceiling.
// Issue ~13-17%, compute pipes idle. 3 reproduced runs: 79.9-81.0us wall.

#define HWDIM 112
#define PLANE (HWDIM * HWDIM)   // 12544
#define ROWS  8
#define BANDS (HWDIM / ROWS)    // 14
#define CHUNK_BYTES (ROWS * HWDIM * 4)   // 3584

__global__ __launch_bounds__(256) void unfold_kernel(
    const float* __restrict__ x, float* __restrict__ out)
{
    __shared__ __align__(16) float sm[9][ROWS][HWDIM];   // 31.5 KB

    const int blk = blockIdx.x;
    const int hb  = blk % BANDS;
    const int nc  = blk / BANDS;            // n*64 + c
    const int h0  = hb * ROWS;

    const int wid  = threadIdx.x >> 5;      // 0..7 -> row h0+wid
    const int lane = threadIdx.x & 31;
    const int h    = h0 + wid;

    const bool wok = lane < 28;
    const int w0 = lane * 4;

    const float* plane = x + (int64_t)nc * PLANE;

    float4 r[3];
#pragma unroll
    for (int i = 0; i < 3; ++i) {
        const int ih = h - 1 + i;
        if (wok && (unsigned)ih < HWDIM)
            r[i] = *reinterpret_cast<const float4*>(plane + ih * HWDIM + w0);
        else
            r[i] = make_float4(0.f, 0.f, 0.f, 0.f);
    }

#pragma unroll
    for (int i = 0; i < 3; ++i) {
        float pw = __shfl_up_sync(0xFFFFFFFFu, r[i].w, 1);
        if (lane == 0) pw = 0.f;                               // left pad
        float nx = __shfl_down_sync(0xFFFFFFFFu, r[i].x, 1);   // lane27 -> 0
        if (wok) {
            *reinterpret_cast<float4*>(&sm[i * 3 + 0][wid][w0]) =
                make_float4(pw, r[i].x, r[i].y, r[i].z);        // kw = -1
            *reinterpret_cast<float4*>(&sm[i * 3 + 1][wid][w0]) = r[i];
            *reinterpret_cast<float4*>(&sm[i * 3 + 2][wid][w0]) =
                make_float4(r[i].y, r[i].z, r[i].w, nx);        // kw = +1
        }
    }

    __syncthreads();
    asm volatile("fence.proxy.async.shared::cta;" ::: "memory");

    // Warp k's lane 0 issues plane k; warp 0 additionally issues plane 8.
    if (lane == 0) {
        const int nplanes = (wid == 0) ? 2 : 1;
#pragma unroll
        for (int q = 0; q < 2; ++q) {
            if (q < nplanes) {
                const int kk = (q == 0) ? wid : 8;
                uint32_t saddr;
                asm("{ .reg .u64 t; cvta.to.shared.u64 t, %1; cvt.u32.u64 %0, t; }"
                    : "=r"(saddr) : "l"(&sm[kk][0][0]));
                float* gdst = out + ((int64_t)(nc * 9 + kk) * HWDIM + h0) * HWDIM;
                asm volatile(
                    "cp.async.bulk.global.shared::cta.bulk_group [%0], [%1], %2;"
                    :: "l"(gdst), "r"(saddr), "n"(CHUNK_BYTES) : "memory");
            }
        }
        asm volatile("cp.async.bulk.commit_group;" ::: "memory");
        asm volatile("cp.async.bulk.wait_group 0;" ::: "memory");
    }
}

extern "C" void kernel_launch(void* const* d_in, const int* in_sizes, int n_in,
                              void* d_out, int out_size)
{
    const float* x = (const float*)d_in[0];
    float* out = (float*)d_out;

    const int blocks = 16 * 64 * BANDS;   // 14336
    unfold_kernel<<<blocks, 256>>>(x, out);
}

// round 12
// speedup vs baseline: 1.0144x; 1.0008x over previous
#include <cuda_runtime.h>
#include <cstdint>

// FINAL (converged, best measured): Unfold (im2col) — SMEM-staged 8-row
// tiles + TMA bulk stores, issue spread across all 8 warps.
// x: [16, 64, 112, 112] f32 ; out: [16, 576, 112, 112] f32
// out[n, c*9 + kh*3 + kw, h, w] = x[n, c, h+kh-1, w+kw-1] (0 outside)
//
// Block = (n, c, 8-row band). Warp w owns row h0+w: 3 aligned float4 loads
// (input L2-resident across the 9x reuse), 9 shifted variants via shfl into
// SMEM; lane 0 of warp k issues the bulk store for plane k (warp 0 also
// issues plane 8) — 9 chunks of 3584B, each 28 full 128B lines.
//
// Roofline evidence (11 rounds): DRAM bytes == compulsory 455MB output
// writes; five store configurations (STG.128, STG.cs, TMA 8/16-row,
// warp-spread TMA, persistent TMA) all plateau at 5.85-6.0 TB/s pure-write
// HBM3e ceiling. Best: 75.6us kernel / 79.9us wall, 6007 GB/s, occ 76%,
// issue 17%, compute pipes idle, rel_err 0.0.

#define HWDIM 112
#define PLANE (HWDIM * HWDIM)   // 12544
#define ROWS  8
#define BANDS (HWDIM / ROWS)    // 14
#define CHUNK_BYTES (ROWS * HWDIM * 4)   // 3584

__global__ __launch_bounds__(256) void unfold_kernel(
    const float* __restrict__ x, float* __restrict__ out)
{
    __shared__ __align__(16) float sm[9][ROWS][HWDIM];   // 31.5 KB

    const int blk = blockIdx.x;
    const int hb  = blk % BANDS;
    const int nc  = blk / BANDS;            // n*64 + c
    const int h0  = hb * ROWS;

    const int wid  = threadIdx.x >> 5;      // 0..7 -> row h0+wid
    const int lane = threadIdx.x & 31;
    const int h    = h0 + wid;

    const bool wok = lane < 28;
    const int w0 = lane * 4;

    const float* plane = x + (int64_t)nc * PLANE;

    float4 r[3];
#pragma unroll
    for (int i = 0; i < 3; ++i) {
        const int ih = h - 1 + i;
        if (wok && (unsigned)ih < HWDIM)
            r[i] = *reinterpret_cast<const float4*>(plane + ih * HWDIM + w0);
        else
            r[i] = make_float4(0.f, 0.f, 0.f, 0.f);
    }

#pragma unroll
    for (int i = 0; i < 3; ++i) {
        float pw = __shfl_up_sync(0xFFFFFFFFu, r[i].w, 1);
        if (lane == 0) pw = 0.f;                               // left pad
        float nx = __shfl_down_sync(0xFFFFFFFFu, r[i].x, 1);   // lane27 -> 0
        if (wok) {
            *reinterpret_cast<float4*>(&sm[i * 3 + 0][wid][w0]) =
                make_float4(pw, r[i].x, r[i].y, r[i].z);        // kw = -1
            *reinterpret_cast<float4*>(&sm[i * 3 + 1][wid][w0]) = r[i];
            *reinterpret_cast<float4*>(&sm[i * 3 + 2][wid][w0]) =
                make_float4(r[i].y, r[i].z, r[i].w, nx);        // kw = +1
        }
    }

    __syncthreads();
    asm volatile("fence.proxy.async.shared::cta;" ::: "memory");

    // Warp k's lane 0 issues plane k; warp 0 additionally issues plane 8.
    if (lane == 0) {
        const int nplanes = (wid == 0) ? 2 : 1;
#pragma unroll
        for (int q = 0; q < 2; ++q) {
            if (q < nplanes) {
                const int kk = (q == 0) ? wid : 8;
                uint32_t saddr;
                asm("{ .reg .u64 t; cvta.to.shared.u64 t, %1; cvt.u32.u64 %0, t; }"
                    : "=r"(saddr) : "l"(&sm[kk][0][0]));
                float* gdst = out + ((int64_t)(nc * 9 + kk) * HWDIM + h0) * HWDIM;
                asm volatile(
                    "cp.async.bulk.global.shared::cta.bulk_group [%0], [%1], %2;"
                    :: "l"(gdst), "r"(saddr), "n"(CHUNK_BYTES) : "memory");
            }
        }
        asm volatile("cp.async.bulk.commit_group;" ::: "memory");
        asm volatile("cp.async.bulk.wait_group 0;" ::: "memory");
    }
}

extern "C" void kernel_launch(void* const* d_in, const int* in_sizes, int n_in,
                              void* d_out, int out_size)
{
    const float* x = (const float*)d_in[0];
    float* out = (float*)d_out;

    const int blocks = 16 * 64 * BANDS;   // 14336
    unfold_kernel<<<blocks, 256>>>(x, out);
}